// round 7
// baseline (speedup 1.0000x reference)
#include <cuda_runtime.h>
#include <math.h>

#define BATCH 4
#define CCH   256
#define HH    64
#define WW    64
#define HWSZ  4096
#define NCC   289   // 17*17 cost-volume channels
#define KO1   144
#define KO2   49

// ---------------- scratch (device globals; no runtime alloc) ----------------
__device__ float g_rnorm[BATCH * HWSZ];             // 1/(||f1||*256)
__device__ float g_cvpart[2][BATCH * NCC * HWSZ];   // costvol raw partials
__device__ float g_matchvol[BATCH * NCC * HWSZ];    // cost volume after leaky relu
__device__ float g_attvol[BATCH * NCC * HWSZ];      // match_vol * att
__device__ float g_h1[BATCH * KO1 * HWSZ];          // after agg1 conv + relu
__device__ float g_part[4][BATCH * KO1 * HWSZ];     // conv split-K partials

// packed fp32x2 FMA: acc += a * b (elementwise on both 32-bit lanes)
__device__ __forceinline__ void fma2(unsigned long long& acc,
                                     unsigned long long a,
                                     unsigned long long b) {
    asm("fma.rn.f32x2 %0, %1, %2, %0;" : "+l"(acc) : "l"(a), "l"(b));
}
__device__ __forceinline__ unsigned long long bcast2(float v) {
    unsigned long long r;
    asm("mov.b64 %0, {%1, %1};" : "=l"(r) : "f"(v));
    return r;
}

// ---------------- K0: per-pixel inverse norm of f1 --------------------------
__global__ void k_rnorm(const float* __restrict__ f1) {
    int p = blockIdx.x * blockDim.x + threadIdx.x;
    int b = p >> 12;
    int sp = p & 4095;
    const float* base = f1 + (size_t)b * CCH * HWSZ + sp;
    float s = 0.f;
#pragma unroll 8
    for (int c = 0; c < CCH; c++) {
        float v = base[c * HWSZ];
        s += v * v;
    }
    float n = fmaxf(sqrtf(s), 1e-12f);
    g_rnorm[p] = 1.f / (n * 256.f);
}

// ---------------- K1: cost volume raw partials (2-way channel split) ---------
#define CV_KC 16
__global__ __launch_bounds__(272) void k_costvol(const float* __restrict__ f1,
                                                 const float* __restrict__ f2) {
    __shared__ float x1s[CV_KC * 64];
    __shared__ float x2s[CV_KC * 24 * 25];

    int tw = blockIdx.x, th = blockIdx.y;
    int b  = blockIdx.z >> 1;
    int s  = blockIdx.z & 1;
    int h0 = th * 8, w0 = tw * 8;

    int t   = threadIdx.x;
    int oj  = t >> 4;
    int pg  = t & 15;
    int py  = pg >> 1;
    int px0 = pg & 1;

    float acc[4][17];
#pragma unroll
    for (int j = 0; j < 4; j++)
#pragma unroll
        for (int i = 0; i < 17; i++) acc[j][i] = 0.f;

    int clo = s * (CCH / 2), chi = clo + CCH / 2;
    for (int c0 = clo; c0 < chi; c0 += CV_KC) {
        __syncthreads();
        for (int i = t; i < CV_KC * 64; i += 272) {
            int cc = i >> 6, pp = i & 63;
            x1s[i] = f1[(((size_t)b * CCH + c0 + cc) * 64 + h0 + (pp >> 3)) * 64 + w0 + (pp & 7)];
        }
        for (int i = t; i < CV_KC * 24 * 24; i += 272) {
            int cc = i / 576;
            int rem = i - cc * 576;
            int r = rem / 24;
            int cx = rem - r * 24;
            int gh = h0 + r - 8, gw = w0 + cx - 8;
            float v = 0.f;
            if (gh >= 0 && gh < 64 && gw >= 0 && gw < 64)
                v = f2[(((size_t)b * CCH + c0 + cc) * 64 + gh) * 64 + gw];
            x2s[cc * 600 + r * 25 + cx] = v;
        }
        __syncthreads();

#pragma unroll 2
        for (int cc = 0; cc < CV_KC; cc++) {
            float x1v[4];
#pragma unroll
            for (int j = 0; j < 4; j++)
                x1v[j] = x1s[cc * 64 + py * 8 + px0 + 2 * j];
            const float* row = &x2s[cc * 600 + (py + oj) * 25 + px0];
            float rv[23];
#pragma unroll
            for (int i = 0; i < 23; i++) rv[i] = row[i];
#pragma unroll
            for (int j = 0; j < 4; j++)
#pragma unroll
                for (int oi = 0; oi < 17; oi++)
                    acc[j][oi] += x1v[j] * rv[2 * j + oi];
        }
    }

    int h = h0 + py;
    float* pout = g_cvpart[s];
#pragma unroll
    for (int j = 0; j < 4; j++) {
        int px = px0 + 2 * j;
        int w = w0 + px;
#pragma unroll
        for (int oi = 0; oi < 17; oi++) {
            int o = oj * 17 + oi;
            pout[((size_t)(b * NCC + o) << 12) + h * 64 + w] = acc[j][oi];
        }
    }
}

// combine costvol partials: (p0+p1)*rnorm, leaky relu -> matchvol
__global__ __launch_bounds__(256) void k_cvcombine() {
    int idx4 = blockIdx.x * blockDim.x + threadIdx.x;
    int total4 = BATCH * NCC * HWSZ / 4;
    if (idx4 >= total4) return;
    int elem = idx4 * 4;
    int b = elem / (NCC * HWSZ);
    int pix = elem & 4095;
    float4 p0 = reinterpret_cast<const float4*>(g_cvpart[0])[idx4];
    float4 p1 = reinterpret_cast<const float4*>(g_cvpart[1])[idx4];
    float4 rn = *reinterpret_cast<const float4*>(&g_rnorm[(b << 12) + pix]);
    float4 v;
    v.x = (p0.x + p1.x) * rn.x;
    v.y = (p0.y + p1.y) * rn.y;
    v.z = (p0.z + p1.z) * rn.z;
    v.w = (p0.w + p1.w) * rn.w;
    v.x = v.x > 0.f ? v.x : 0.1f * v.x;
    v.y = v.y > 0.f ? v.y : 0.1f * v.y;
    v.z = v.z > 0.f ? v.z : 0.1f * v.z;
    v.w = v.w > 0.f ? v.w : 0.1f * v.w;
    reinterpret_cast<float4*>(g_matchvol)[idx4] = v;
}

// ---------------- K2: depthwise 7x7 attention + gate -------------------------
__global__ __launch_bounds__(256) void k_dw(const float* __restrict__ w7,
                                            const float* __restrict__ b7) {
    __shared__ float tile[70 * 70];
    __shared__ float wsh[49];
    int bo = blockIdx.x;
    int o = bo % NCC;
    const float* src = g_matchvol + (size_t)bo * HWSZ;
    int t = threadIdx.x;

    for (int i = t; i < 4900; i += 256) {
        int r = i / 70, c = i - r * 70;
        int gy = r - 3, gx = c - 3;
        tile[i] = (gy >= 0 && gy < 64 && gx >= 0 && gx < 64) ? src[gy * 64 + gx] : 0.f;
    }
    if (t < 49) wsh[t] = w7[o * 49 + t];
    __syncthreads();

    float bv = b7[o];
    for (int i = t; i < HWSZ; i += 256) {
        int y = i >> 6, x = i & 63;
        float a = bv;
#pragma unroll
        for (int ky = 0; ky < 7; ky++)
#pragma unroll
            for (int kx = 0; kx < 7; kx++)
                a += wsh[ky * 7 + kx] * tile[(y + ky) * 70 + x + kx];
        float mv = tile[(y + 3) * 70 + x + 3];
        g_attvol[(size_t)bo * HWSZ + i] = mv * a;
    }
}

// ---------------- K3/K4: 3x3 conv split-K partial (packed f32x2 FMA) ---------
// Block tile: KOT out channels x (ROWS x 64) positions. Threads = KOTH*32.
// Thread tile: 8 ko (4 packed pairs) x TN positions. SEL: 0 = attvol, 1 = h1.
// KCc = 8 keeps smem ~27KB; __launch_bounds__(..., 3) forces 3 blocks/SM.
template <int KOT, int KOTH, int ROWS, int CIN, int KOTOT, int NSPLIT, int SEL>
__global__ __launch_bounds__(KOTH * 32, 3) void k_conv3(const float* __restrict__ wgt) {
    constexpr int TN = 2 * ROWS;
    constexpr int KCc = 8;
    constexpr int IW = 66;
    constexpr int IR = ROWS + 2;
    constexpr int NTHR = KOTH * 32;
    constexpr int CBT = 64 / TN;
    constexpr int CPS = (((CIN + NSPLIT - 1) / NSPLIT) + KCc - 1) / KCc * KCc;

    __shared__ float in_s[KCc * IR * IW];
    __shared__ float w_s[KCc * 9][KOT];

    const float* in = (SEL == 0) ? g_attvol : g_h1;

    int koB = blockIdx.x, rg = blockIdx.y;
    int b = blockIdx.z / NSPLIT;
    int s = blockIdx.z % NSPLIT;
    int cbeg = s * CPS;
    int cend = (cbeg + CPS < CIN) ? (cbeg + CPS) : CIN;

    int y0 = rg * ROWS;
    int tid = threadIdx.x;
    int kot = tid >> 5, pt = tid & 31;
    int r = pt / CBT, cb = pt % CBT;

    unsigned long long acc[4][TN];
#pragma unroll
    for (int mp = 0; mp < 4; mp++)
#pragma unroll
        for (int j = 0; j < TN; j++) acc[mp][j] = 0ull;

    const float* inb = in + (size_t)b * CIN * HWSZ;

    for (int ci0 = cbeg; ci0 < cend; ci0 += KCc) {
        __syncthreads();
        for (int i = tid; i < KCc * IR * IW; i += NTHR) {
            int cc = i / (IR * IW);
            int rem = i - cc * (IR * IW);
            int rr = rem / IW;
            int c = rem - rr * IW;
            int gy = y0 + rr - 1, gx = c - 1, ci = ci0 + cc;
            float v = 0.f;
            if (ci < cend && gy >= 0 && gy < 64 && gx >= 0 && gx < 64)
                v = inb[((size_t)ci * 64 + gy) * 64 + gx];
            in_s[i] = v;
        }
        for (int i = tid; i < KCc * 9 * KOT; i += NTHR) {
            int kos = i / (KCc * 9);
            int kk = i - kos * (KCc * 9);
            int cc = kk / 9;
            int q = kk - cc * 9;
            int ko = koB * KOT + kos, ci = ci0 + cc;
            float v = 0.f;
            if (ko < KOTOT && ci < cend)
                v = wgt[((size_t)ko * CIN + ci) * 9 + q];
            w_s[kk][kos] = v;
        }
        __syncthreads();

#pragma unroll 1
        for (int cc = 0; cc < KCc; cc++) {
#pragma unroll
            for (int ky = 0; ky < 3; ky++) {
                const float* irow = &in_s[(cc * IR + r + ky) * IW + cb * TN];
                unsigned long long rb[TN + 2];
#pragma unroll
                for (int j = 0; j < TN + 2; j++) rb[j] = bcast2(irow[j]);
#pragma unroll
                for (int kx = 0; kx < 3; kx++) {
                    int kk = cc * 9 + ky * 3 + kx;
                    // LDS.128: register pairs are already packed f32x2 operands
                    const ulonglong2* wp =
                        reinterpret_cast<const ulonglong2*>(&w_s[kk][kot * 8]);
                    ulonglong2 wq0 = wp[0], wq1 = wp[1];
#pragma unroll
                    for (int j = 0; j < TN; j++) fma2(acc[0][j], wq0.x, rb[kx + j]);
#pragma unroll
                    for (int j = 0; j < TN; j++) fma2(acc[1][j], wq0.y, rb[kx + j]);
#pragma unroll
                    for (int j = 0; j < TN; j++) fma2(acc[2][j], wq1.x, rb[kx + j]);
#pragma unroll
                    for (int j = 0; j < TN; j++) fma2(acc[3][j], wq1.y, rb[kx + j]);
                }
            }
        }
    }

    // epilogue: store raw partial sums (bias+relu in combine)
    float* pout = g_part[s];
#pragma unroll
    for (int mp = 0; mp < 4; mp++) {
        int ko0 = koB * KOT + kot * 8 + 2 * mp;
#pragma unroll
        for (int half = 0; half < 2; half++) {
            int ko = ko0 + half;
            if (ko < KOTOT) {
                float* op = pout + (((size_t)b * KOTOT + ko) * 64 + (y0 + r)) * 64 + cb * TN;
#pragma unroll
                for (int j = 0; j < TN; j++) {
                    float2 v = *reinterpret_cast<float2*>(&acc[mp][j]);
                    op[j] = half ? v.y : v.x;
                }
            }
        }
    }
}

// ---------------- combine: sum NSPLIT partials + bias + relu -------------------
template <int KOTOT, int NSPLIT>
__global__ __launch_bounds__(256) void k_combine(const float* __restrict__ bias,
                                                 float* __restrict__ dout) {
    int idx4 = blockIdx.x * blockDim.x + threadIdx.x;
    int total4 = BATCH * KOTOT * HWSZ / 4;
    if (idx4 >= total4) return;
    int ko = ((idx4 * 4) >> 12) % KOTOT;
    float4 a = reinterpret_cast<const float4*>(g_part[0])[idx4];
#pragma unroll
    for (int s = 1; s < NSPLIT; s++) {
        float4 p = reinterpret_cast<const float4*>(g_part[s])[idx4];
        a.x += p.x; a.y += p.y; a.z += p.z; a.w += p.w;
    }
    float bv = bias[ko];
    float4 v;
    v.x = fmaxf(a.x + bv, 0.f);
    v.y = fmaxf(a.y + bv, 0.f);
    v.z = fmaxf(a.z + bv, 0.f);
    v.w = fmaxf(a.w + bv, 0.f);
    reinterpret_cast<float4*>(dout)[idx4] = v;
}

// ---------------- launch ------------------------------------------------------
extern "C" void kernel_launch(void* const* d_in, const int* in_sizes, int n_in,
                              void* d_out, int out_size) {
    const float* f1    = (const float*)d_in[0];
    const float* f2    = (const float*)d_in[1];
    const float* att_w = (const float*)d_in[2];
    const float* att_b = (const float*)d_in[3];
    const float* a1w   = (const float*)d_in[4];
    const float* a1b   = (const float*)d_in[5];
    const float* a2w   = (const float*)d_in[6];
    const float* a2b   = (const float*)d_in[7];
    float* out = (float*)d_out;

    k_rnorm<<<BATCH * HWSZ / 256, 256>>>(f1);

    // cost volume: 2-way channel split, 512 blocks
    dim3 gcv(8, 8, BATCH * 2);
    k_costvol<<<gcv, 272>>>(f1, f2);
    {
        int total4 = BATCH * NCC * HWSZ / 4;
        k_cvcombine<<<(total4 + 255) / 256, 256>>>();
    }

    k_dw<<<BATCH * NCC, 256>>>(att_w, att_b);

    // conv1: 289 -> 144, KOT=48 (3 blocks), ROWS=4 (TN=8), 4-way split-K
    dim3 g1(3, 16, BATCH * 4);
    k_conv3<48, 6, 4, NCC, KO1, 4, 0><<<g1, 192>>>(a1w);
    {
        float* h1p = nullptr;
        cudaGetSymbolAddress((void**)&h1p, g_h1);
        int total4 = BATCH * KO1 * HWSZ / 4;
        k_combine<KO1, 4><<<(total4 + 255) / 256, 256>>>(a1b, h1p);
    }

    // conv2: 144 -> 49, KOT=56 (1 block), ROWS=2 (TN=4), 3-way split-K (48 each)
    dim3 g2(1, 32, BATCH * 3);
    k_conv3<56, 7, 2, KO1, KO2, 3, 1><<<g2, 224>>>(a2w);
    {
        int total4 = BATCH * KO2 * HWSZ / 4;
        k_combine<KO2, 3><<<(total4 + 255) / 256, 256>>>(a2b, out);
    }
}

// round 8
// speedup vs baseline: 1.0873x; 1.0873x over previous
#include <cuda_runtime.h>
#include <math.h>

#define BATCH 4
#define CCH   256
#define HH    64
#define WW    64
#define HWSZ  4096
#define NCC   289   // 17*17 cost-volume channels
#define KO1   144
#define KO2   49

// ---------------- scratch (device globals; no runtime alloc) ----------------
__device__ float g_rnorm[BATCH * HWSZ];             // 1/(||f1||*256)
__device__ float g_cvpart[2][BATCH * NCC * HWSZ];   // costvol raw partials
__device__ float g_matchvol[BATCH * NCC * HWSZ];    // cost volume after leaky relu
__device__ float g_attvol[BATCH * NCC * HWSZ];      // match_vol * att
__device__ float g_h1[BATCH * KO1 * HWSZ];          // after agg1 conv + relu
__device__ float g_part[4][BATCH * KO1 * HWSZ];     // conv split-K partials

// packed fp32x2 FMA: acc += a * b (elementwise on both 32-bit lanes)
__device__ __forceinline__ void fma2(unsigned long long& acc,
                                     unsigned long long a,
                                     unsigned long long b) {
    asm("fma.rn.f32x2 %0, %1, %2, %0;" : "+l"(acc) : "l"(a), "l"(b));
}
__device__ __forceinline__ unsigned long long bcast2(float v) {
    unsigned long long r;
    asm("mov.b64 %0, {%1, %1};" : "=l"(r) : "f"(v));
    return r;
}
__device__ __forceinline__ unsigned long long pack2(float lo, float hi) {
    unsigned long long r;
    asm("mov.b64 %0, {%1, %2};" : "=l"(r) : "f"(lo), "f"(hi));
    return r;
}

// ---------------- K0: per-pixel inverse norm of f1 --------------------------
__global__ void k_rnorm(const float* __restrict__ f1) {
    int p = blockIdx.x * blockDim.x + threadIdx.x;
    int b = p >> 12;
    int sp = p & 4095;
    const float* base = f1 + (size_t)b * CCH * HWSZ + sp;
    float s = 0.f;
#pragma unroll 8
    for (int c = 0; c < CCH; c++) {
        float v = base[c * HWSZ];
        s += v * v;
    }
    float n = fmaxf(sqrtf(s), 1e-12f);
    g_rnorm[p] = 1.f / (n * 256.f);
}

// ---------------- K1: cost volume raw partials (2-way split, f32x2 core) -----
#define CV_KC 16
__global__ __launch_bounds__(272) void k_costvol(const float* __restrict__ f1,
                                                 const float* __restrict__ f2) {
    __shared__ float x1s[CV_KC * 64];
    __shared__ float x2s[CV_KC * 24 * 25];

    int tw = blockIdx.x, th = blockIdx.y;
    int b  = blockIdx.z >> 1;
    int s  = blockIdx.z & 1;
    int h0 = th * 8, w0 = tw * 8;

    int t   = threadIdx.x;
    int oj  = t >> 4;
    int pg  = t & 15;
    int py  = pg >> 1;
    int px0 = pg & 1;

    // packed accumulators: acc2[j][p] holds (oi=2p, oi=2p+1); accS[j] = oi 16
    unsigned long long acc2[4][8];
    float accS[4];
#pragma unroll
    for (int j = 0; j < 4; j++) {
        accS[j] = 0.f;
#pragma unroll
        for (int p = 0; p < 8; p++) acc2[j][p] = 0ull;
    }

    int clo = s * (CCH / 2), chi = clo + CCH / 2;
    for (int c0 = clo; c0 < chi; c0 += CV_KC) {
        __syncthreads();
        for (int i = t; i < CV_KC * 64; i += 272) {
            int cc = i >> 6, pp = i & 63;
            x1s[i] = f1[(((size_t)b * CCH + c0 + cc) * 64 + h0 + (pp >> 3)) * 64 + w0 + (pp & 7)];
        }
        for (int i = t; i < CV_KC * 24 * 24; i += 272) {
            int cc = i / 576;
            int rem = i - cc * 576;
            int r = rem / 24;
            int cx = rem - r * 24;
            int gh = h0 + r - 8, gw = w0 + cx - 8;
            float v = 0.f;
            if (gh >= 0 && gh < 64 && gw >= 0 && gw < 64)
                v = f2[(((size_t)b * CCH + c0 + cc) * 64 + gh) * 64 + gw];
            x2s[cc * 600 + r * 25 + cx] = v;
        }
        __syncthreads();

#pragma unroll 2
        for (int cc = 0; cc < CV_KC; cc++) {
            float x1v[4];
            unsigned long long x1b[4];
#pragma unroll
            for (int j = 0; j < 4; j++) {
                x1v[j] = x1s[cc * 64 + py * 8 + px0 + 2 * j];
                x1b[j] = bcast2(x1v[j]);
            }
            const float* row = &x2s[cc * 600 + (py + oj) * 25 + px0];
            float rv[23];
#pragma unroll
            for (int i = 0; i < 23; i++) rv[i] = row[i];
            unsigned long long rp[11];
#pragma unroll
            for (int k = 0; k < 11; k++) rp[k] = pack2(rv[2 * k], rv[2 * k + 1]);
#pragma unroll
            for (int j = 0; j < 4; j++) {
#pragma unroll
                for (int p = 0; p < 8; p++)
                    fma2(acc2[j][p], x1b[j], rp[j + p]);
                accS[j] += x1v[j] * rv[2 * j + 16];
            }
        }
    }

    int h = h0 + py;
    float* pout = g_cvpart[s];
#pragma unroll
    for (int j = 0; j < 4; j++) {
        int px = px0 + 2 * j;
        int w = w0 + px;
        size_t base = ((size_t)b * NCC << 12) + ((size_t)oj * 17 << 12) + h * 64 + w;
#pragma unroll
        for (int p = 0; p < 8; p++) {
            float2 v = *reinterpret_cast<float2*>(&acc2[j][p]);
            pout[base + ((size_t)(2 * p) << 12)]     = v.x;
            pout[base + ((size_t)(2 * p + 1) << 12)] = v.y;
        }
        pout[base + ((size_t)16 << 12)] = accS[j];
    }
}

// combine costvol partials: (p0+p1)*rnorm, leaky relu -> matchvol
__global__ __launch_bounds__(256) void k_cvcombine() {
    int idx4 = blockIdx.x * blockDim.x + threadIdx.x;
    int total4 = BATCH * NCC * HWSZ / 4;
    if (idx4 >= total4) return;
    int elem = idx4 * 4;
    int b = elem / (NCC * HWSZ);
    int pix = elem & 4095;
    float4 p0 = reinterpret_cast<const float4*>(g_cvpart[0])[idx4];
    float4 p1 = reinterpret_cast<const float4*>(g_cvpart[1])[idx4];
    float4 rn = *reinterpret_cast<const float4*>(&g_rnorm[(b << 12) + pix]);
    float4 v;
    v.x = (p0.x + p1.x) * rn.x;
    v.y = (p0.y + p1.y) * rn.y;
    v.z = (p0.z + p1.z) * rn.z;
    v.w = (p0.w + p1.w) * rn.w;
    v.x = v.x > 0.f ? v.x : 0.1f * v.x;
    v.y = v.y > 0.f ? v.y : 0.1f * v.y;
    v.z = v.z > 0.f ? v.z : 0.1f * v.z;
    v.w = v.w > 0.f ? v.w : 0.1f * v.w;
    reinterpret_cast<float4*>(g_matchvol)[idx4] = v;
}

// ---------------- K2: depthwise 7x7 attention + gate (4-wide) ----------------
__global__ __launch_bounds__(256) void k_dw(const float* __restrict__ w7,
                                            const float* __restrict__ b7) {
    __shared__ float tile[70 * 70];
    __shared__ float wsh[49];
    int bo = blockIdx.x;
    int o = bo % NCC;
    const float* src = g_matchvol + (size_t)bo * HWSZ;
    int t = threadIdx.x;

    for (int i = t; i < 4900; i += 256) {
        int r = i / 70, c = i - r * 70;
        int gy = r - 3, gx = c - 3;
        tile[i] = (gy >= 0 && gy < 64 && gx >= 0 && gx < 64) ? src[gy * 64 + gx] : 0.f;
    }
    if (t < 49) wsh[t] = w7[o * 49 + t];
    __syncthreads();

    float bv = b7[o];
    float* dst = g_attvol + (size_t)bo * HWSZ;
#pragma unroll
    for (int gg = 0; gg < 4; gg++) {
        int g = gg * 256 + t;          // 0..1023 pixel groups of 4
        int y = g >> 4;
        int x0 = (g & 15) * 4;
        float a0 = bv, a1 = bv, a2 = bv, a3 = bv;
        float mv0, mv1, mv2, mv3;
#pragma unroll
        for (int ky = 0; ky < 7; ky++) {
            const float* row = &tile[(y + ky) * 70 + x0];
            float rw[10];
#pragma unroll
            for (int i = 0; i < 10; i++) rw[i] = row[i];
            if (ky == 3) { mv0 = rw[3]; mv1 = rw[4]; mv2 = rw[5]; mv3 = rw[6]; }
#pragma unroll
            for (int kx = 0; kx < 7; kx++) {
                float wv = wsh[ky * 7 + kx];
                a0 += wv * rw[kx];
                a1 += wv * rw[kx + 1];
                a2 += wv * rw[kx + 2];
                a3 += wv * rw[kx + 3];
            }
        }
        float4 outv;
        outv.x = mv0 * a0;
        outv.y = mv1 * a1;
        outv.z = mv2 * a2;
        outv.w = mv3 * a3;
        *reinterpret_cast<float4*>(&dst[y * 64 + x0]) = outv;
    }
}

// ---------------- K3/K4: 3x3 conv split-K partial (packed f32x2 FMA) ---------
// Round-6 proven version: pack2 weights, KCc=8, __launch_bounds__(.,3).
template <int KOT, int KOTH, int ROWS, int CIN, int KOTOT, int NSPLIT, int SEL>
__global__ __launch_bounds__(KOTH * 32, 3) void k_conv3(const float* __restrict__ wgt) {
    constexpr int TN = 2 * ROWS;
    constexpr int KCc = 8;
    constexpr int IW = 66;
    constexpr int IR = ROWS + 2;
    constexpr int NTHR = KOTH * 32;
    constexpr int CBT = 64 / TN;
    constexpr int CPS = (((CIN + NSPLIT - 1) / NSPLIT) + KCc - 1) / KCc * KCc;

    __shared__ float in_s[KCc * IR * IW];
    __shared__ float w_s[KCc * 9][KOT];

    const float* in = (SEL == 0) ? g_attvol : g_h1;

    int koB = blockIdx.x, rg = blockIdx.y;
    int b = blockIdx.z / NSPLIT;
    int s = blockIdx.z % NSPLIT;
    int cbeg = s * CPS;
    int cend = (cbeg + CPS < CIN) ? (cbeg + CPS) : CIN;

    int y0 = rg * ROWS;
    int tid = threadIdx.x;
    int kot = tid >> 5, pt = tid & 31;
    int r = pt / CBT, cb = pt % CBT;

    unsigned long long acc[4][TN];
#pragma unroll
    for (int mp = 0; mp < 4; mp++)
#pragma unroll
        for (int j = 0; j < TN; j++) acc[mp][j] = 0ull;

    const float* inb = in + (size_t)b * CIN * HWSZ;

    for (int ci0 = cbeg; ci0 < cend; ci0 += KCc) {
        __syncthreads();
        for (int i = tid; i < KCc * IR * IW; i += NTHR) {
            int cc = i / (IR * IW);
            int rem = i - cc * (IR * IW);
            int rr = rem / IW;
            int c = rem - rr * IW;
            int gy = y0 + rr - 1, gx = c - 1, ci = ci0 + cc;
            float v = 0.f;
            if (ci < cend && gy >= 0 && gy < 64 && gx >= 0 && gx < 64)
                v = inb[((size_t)ci * 64 + gy) * 64 + gx];
            in_s[i] = v;
        }
        for (int i = tid; i < KCc * 9 * KOT; i += NTHR) {
            int kos = i / (KCc * 9);
            int kk = i - kos * (KCc * 9);
            int cc = kk / 9;
            int q = kk - cc * 9;
            int ko = koB * KOT + kos, ci = ci0 + cc;
            float v = 0.f;
            if (ko < KOTOT && ci < cend)
                v = wgt[((size_t)ko * CIN + ci) * 9 + q];
            w_s[kk][kos] = v;
        }
        __syncthreads();

#pragma unroll 1
        for (int cc = 0; cc < KCc; cc++) {
#pragma unroll
            for (int ky = 0; ky < 3; ky++) {
                const float* irow = &in_s[(cc * IR + r + ky) * IW + cb * TN];
                unsigned long long rb[TN + 2];
#pragma unroll
                for (int j = 0; j < TN + 2; j++) rb[j] = bcast2(irow[j]);
#pragma unroll
                for (int kx = 0; kx < 3; kx++) {
                    int kk = cc * 9 + ky * 3 + kx;
                    const float4* wp = reinterpret_cast<const float4*>(&w_s[kk][kot * 8]);
                    float4 wa = wp[0], wb = wp[1];
                    unsigned long long w2[4];
                    w2[0] = pack2(wa.x, wa.y);
                    w2[1] = pack2(wa.z, wa.w);
                    w2[2] = pack2(wb.x, wb.y);
                    w2[3] = pack2(wb.z, wb.w);
#pragma unroll
                    for (int mp = 0; mp < 4; mp++)
#pragma unroll
                        for (int j = 0; j < TN; j++)
                            fma2(acc[mp][j], w2[mp], rb[kx + j]);
                }
            }
        }
    }

    float* pout = g_part[s];
#pragma unroll
    for (int mp = 0; mp < 4; mp++) {
        int ko0 = koB * KOT + kot * 8 + 2 * mp;
#pragma unroll
        for (int half = 0; half < 2; half++) {
            int ko = ko0 + half;
            if (ko < KOTOT) {
                float* op = pout + (((size_t)b * KOTOT + ko) * 64 + (y0 + r)) * 64 + cb * TN;
#pragma unroll
                for (int j = 0; j < TN; j++) {
                    float2 v = *reinterpret_cast<float2*>(&acc[mp][j]);
                    op[j] = half ? v.y : v.x;
                }
            }
        }
    }
}

// ---------------- combine: sum NSPLIT partials + bias + relu -------------------
template <int KOTOT, int NSPLIT>
__global__ __launch_bounds__(256) void k_combine(const float* __restrict__ bias,
                                                 float* __restrict__ dout) {
    int idx4 = blockIdx.x * blockDim.x + threadIdx.x;
    int total4 = BATCH * KOTOT * HWSZ / 4;
    if (idx4 >= total4) return;
    int ko = ((idx4 * 4) >> 12) % KOTOT;
    float4 a = reinterpret_cast<const float4*>(g_part[0])[idx4];
#pragma unroll
    for (int s = 1; s < NSPLIT; s++) {
        float4 p = reinterpret_cast<const float4*>(g_part[s])[idx4];
        a.x += p.x; a.y += p.y; a.z += p.z; a.w += p.w;
    }
    float bv = bias[ko];
    float4 v;
    v.x = fmaxf(a.x + bv, 0.f);
    v.y = fmaxf(a.y + bv, 0.f);
    v.z = fmaxf(a.z + bv, 0.f);
    v.w = fmaxf(a.w + bv, 0.f);
    reinterpret_cast<float4*>(dout)[idx4] = v;
}

// ---------------- launch ------------------------------------------------------
extern "C" void kernel_launch(void* const* d_in, const int* in_sizes, int n_in,
                              void* d_out, int out_size) {
    const float* f1    = (const float*)d_in[0];
    const float* f2    = (const float*)d_in[1];
    const float* att_w = (const float*)d_in[2];
    const float* att_b = (const float*)d_in[3];
    const float* a1w   = (const float*)d_in[4];
    const float* a1b   = (const float*)d_in[5];
    const float* a2w   = (const float*)d_in[6];
    const float* a2b   = (const float*)d_in[7];
    float* out = (float*)d_out;

    k_rnorm<<<BATCH * HWSZ / 256, 256>>>(f1);

    // cost volume: 2-way channel split, 512 blocks, f32x2 inner loop
    dim3 gcv(8, 8, BATCH * 2);
    k_costvol<<<gcv, 272>>>(f1, f2);
    {
        int total4 = BATCH * NCC * HWSZ / 4;
        k_cvcombine<<<(total4 + 255) / 256, 256>>>();
    }

    k_dw<<<BATCH * NCC, 256>>>(att_w, att_b);

    // conv1: 289 -> 144, KOT=48 (3 blocks), ROWS=4 (TN=8), 4-way split-K
    dim3 g1(3, 16, BATCH * 4);
    k_conv3<48, 6, 4, NCC, KO1, 4, 0><<<g1, 192>>>(a1w);
    {
        float* h1p = nullptr;
        cudaGetSymbolAddress((void**)&h1p, g_h1);
        int total4 = BATCH * KO1 * HWSZ / 4;
        k_combine<KO1, 4><<<(total4 + 255) / 256, 256>>>(a1b, h1p);
    }

    // conv2: 144 -> 49, KOT=56 (1 block), ROWS=2 (TN=4), 3-way split-K (48 each)
    dim3 g2(1, 32, BATCH * 3);
    k_conv3<56, 7, 2, KO1, KO2, 3, 1><<<g2, 224>>>(a2w);
    {
        int total4 = BATCH * KO2 * HWSZ / 4;
        k_combine<KO2, 3><<<(total4 + 255) / 256, 256>>>(a2b, out);
    }
}